// round 5
// baseline (speedup 1.0000x reference)
#include <cuda_runtime.h>
#include <math.h>

#define BB 32
#define SS 512
#define HH 768
#define MC 128
#define EPSF 1e-8f
#define TK 16

// ---------------- scratch (static device memory; no allocs) ----------------
__device__ float g_keyconf[BB*SS];
__device__ float g_valconf[BB*SS];
__device__ int   g_kidx[BB*MC];
__device__ int   g_vidx[BB*MC];
__device__ float g_kbox[BB*MC*4];
__device__ float g_vbox[BB*MC*4];
__device__ float g_tmpA[BB*MC*HH];
__device__ float g_tmpB[BB*MC*HH];
__device__ float g_biaf4[4][BB*MC*MC];
__device__ float g_Wc[HH*HH];
__device__ float g_M[HH*HH];
__device__ float g_bc[HH];     // s1 = bk @ Wbil
__device__ float g_p[HH];      // p  = Wc @ bv
__device__ float g_q[HH];      // q  = s1 @ Wv^T
__device__ float g_c[1];       // c  = s1 . bv
__device__ float g_rowk[BB*MC];
__device__ float g_rowv[BB*MC];

// ---------------- 1) softmax + argmax + mask ----------------
__global__ void conf_kernel(const float* __restrict__ logits,
                            const int* __restrict__ mask) {
    int t = blockIdx.x * blockDim.x + threadIdx.x;
    if (t >= BB * SS) return;
    float l0 = logits[3*t+0], l1 = logits[3*t+1], l2 = logits[3*t+2];
    int pred = 0; float best = l0;
    if (l1 > best) { pred = 1; best = l1; }
    if (l2 > best) { pred = 2; best = l2; }
    float e0 = expf(l0 - best), e1 = expf(l1 - best), e2 = expf(l2 - best);
    float inv = 1.0f / (e0 + e1 + e2);
    bool valid = (mask[t] == 1);
    float ninf = -INFINITY;
    g_keyconf[t] = (pred == 1 && valid) ? e1 * inv : ninf;
    g_valconf[t] = (pred == 2 && valid) ? e2 * inv : ninf;
}

// ---------------- 2) exact top-128 of 512 via bitonic sort ----------------
__global__ void topk_kernel(const float* __restrict__ bboxes,
                            float* __restrict__ out) {
    int b = blockIdx.x;
    int which = blockIdx.y;   // 0 = key, 1 = val
    const float* conf = (which == 0) ? g_keyconf : g_valconf;
    __shared__ float sc[512];
    __shared__ int   si[512];
    int tid = threadIdx.x;
    sc[tid] = conf[b * SS + tid];
    si[tid] = tid;

    for (int k = 2; k <= 512; k <<= 1) {
        for (int j = k >> 1; j > 0; j >>= 1) {
            __syncthreads();
            int ixj = tid ^ j;
            if (ixj > tid) {
                float c1 = sc[tid], c2 = sc[ixj];
                int   i1 = si[tid], i2 = si[ixj];
                bool b2 = (c2 > c1) || (c2 == c1 && i2 < i1);
                bool doswap = ((tid & k) == 0) ? b2 : !b2;
                if (doswap) {
                    sc[tid] = c2; si[tid] = i2;
                    sc[ixj] = c1; si[ixj] = i1;
                }
            }
        }
    }
    __syncthreads();

    if (tid < MC) {
        int   idx = si[tid];
        float cf  = sc[tid];
        int*   gi = (which == 0) ? g_kidx : g_vidx;
        float* gb = (which == 0) ? g_kbox : g_vbox;
        gi[b * MC + tid] = idx;
        const float* src = bboxes + ((long long)b * SS + idx) * 4;
        float* dst = gb + (b * MC + tid) * 4;
        dst[0] = src[0]; dst[1] = src[1]; dst[2] = src[2]; dst[3] = src[3];
        long long base = (long long)BB * MC * MC;            // 524288
        float vf = (cf != -INFINITY) ? 1.0f : 0.0f;
        out[base + (long long)which * (BB * MC) + b * MC + tid] = vf;
        out[base + 2LL * (BB * MC) + (long long)which * (BB * MC) + b * MC + tid] = (float)idx;
    }
}

// ---------------- s1[j] = sum_h bk[h] * Wbil[h,j] ----------------
__global__ void bc_kernel(const float* __restrict__ bk,
                          const float* __restrict__ Wbil) {
    int j = blockIdx.x * 128 + threadIdx.x;
    float s = 0.0f;
    for (int h = 0; h < HH; h++) s = fmaf(bk[h], Wbil[h * HH + j], s);
    g_bc[j] = s;
}

// ---------------- generic row dot: out[r] = A[r,:] . x  (warp per row) ----
__global__ void rowdot_kernel(const float* __restrict__ A,
                              const float* __restrict__ x,
                              float* __restrict__ out) {
    int w = (blockIdx.x * blockDim.x + threadIdx.x) >> 5;
    int lane = threadIdx.x & 31;
    const float* row = A + (long long)w * HH;
    float s = 0.f;
    #pragma unroll 4
    for (int cdx = lane; cdx < HH; cdx += 32) s = fmaf(row[cdx], x[cdx], s);
    #pragma unroll
    for (int o = 16; o; o >>= 1) s += __shfl_xor_sync(0xffffffffu, s, o);
    if (lane == 0) out[w] = s;
}

// ---------------- c = s1 . bv ----------------
__global__ void cdot_kernel(const float* __restrict__ bv) {
    __shared__ float red[256];
    int t = threadIdx.x;
    float s = 0.f;
    for (int g = t; g < HH; g += 256) s = fmaf(g_bc[g], bv[g], s);
    red[t] = s; __syncthreads();
    for (int o = 128; o; o >>= 1) { if (t < o) red[t] += red[t + o]; __syncthreads(); }
    if (t == 0) g_c[0] = red[0];
}

// ---------------- gathered row dots: rowk = Gk.p ; rowv = Gv.q + c --------
__global__ void growdot_kernel(const float* __restrict__ seq) {
    int r = blockIdx.x * 8 + (threadIdx.x >> 5);   // 0..4095
    int lane = threadIdx.x & 31;
    int which = blockIdx.y;
    const int* gidx = which ? g_vidx : g_kidx;
    const float* vec = which ? g_q : g_p;
    const float* row = seq + ((long long)(r >> 7) * SS + gidx[r]) * HH;
    float s = 0.f;
    #pragma unroll 4
    for (int cdx = lane; cdx < HH; cdx += 32) s = fmaf(row[cdx], vec[cdx], s);
    #pragma unroll
    for (int o = 16; o; o >>= 1) s += __shfl_xor_sync(0xffffffffu, s, o);
    if (lane == 0) {
        if (which) g_rowv[r] = s + g_c[0];
        else       g_rowk[r] = s;
    }
}

// ---------------- NN split-K, atomic epilogue (Wc = Wk @ Wbil) ------------
__global__ __launch_bounds__(512)
void nn_atomic(const float* __restrict__ A, const float* __restrict__ B,
               float* __restrict__ C, int nslabs) {
    __shared__ __align__(16) float As[2][TK][132];
    __shared__ __align__(16) float Bs[2][TK][128];
    int tid = threadIdx.x;
    int tx = tid & 15, ty = tid >> 4;
    int m0 = blockIdx.y * 128, c0 = blockIdx.x * 128;
    int kbase = blockIdx.z * nslabs * TK;
    int ar = tid >> 2, ak = (tid & 3) * 4;
    int bkr = tid >> 5, bcc = (tid & 31) * 4;

    float4 av, bv4;
#define LOAD(K0) do { \
        av  = *(const float4*)(A + (long long)(m0 + ar) * HH + (K0) + ak); \
        bv4 = *(const float4*)(B + (long long)((K0) + bkr) * HH + c0 + bcc); \
    } while (0)
#define STORE(BUF) do { \
        As[BUF][ak+0][ar] = av.x; As[BUF][ak+1][ar] = av.y; \
        As[BUF][ak+2][ar] = av.z; As[BUF][ak+3][ar] = av.w; \
        *(float4*)&Bs[BUF][bkr][bcc] = bv4; \
    } while (0)

    float acc[4][8];
    #pragma unroll
    for (int i = 0; i < 4; i++)
        #pragma unroll
        for (int j = 0; j < 8; j++) acc[i][j] = 0.f;

    LOAD(kbase); STORE(0); __syncthreads();
    for (int kt = 0; kt < nslabs; kt++) {
        int cur = kt & 1;
        if (kt + 1 < nslabs) LOAD(kbase + (kt + 1) * TK);
        #pragma unroll
        for (int kk = 0; kk < TK; kk++) {
            float a[4], b[8];
            *(float4*)a       = *(const float4*)&As[cur][kk][ty * 4];
            *(float4*)b       = *(const float4*)&Bs[cur][kk][tx * 8];
            *(float4*)(b + 4) = *(const float4*)&Bs[cur][kk][tx * 8 + 4];
            #pragma unroll
            for (int i = 0; i < 4; i++)
                #pragma unroll
                for (int j = 0; j < 8; j++)
                    acc[i][j] = fmaf(a[i], b[j], acc[i][j]);
        }
        if (kt + 1 < nslabs) { STORE(cur ^ 1); __syncthreads(); }
    }
    #pragma unroll
    for (int i = 0; i < 4; i++)
        #pragma unroll
        for (int j = 0; j < 8; j++)
            atomicAdd(&C[(long long)(m0 + ty * 4 + i) * HH + c0 + tx * 8 + j], acc[i][j]);
#undef LOAD
#undef STORE
}

// ---------------- NT split-K, atomic epilogue (M = Wc @ Wv^T) -------------
__global__ __launch_bounds__(512)
void nt_atomic(const float* __restrict__ A, const float* __restrict__ B,
               float* __restrict__ C, int nslabs) {
    __shared__ __align__(16) float As[2][TK][132];
    __shared__ __align__(16) float Bs[2][TK][132];
    int tid = threadIdx.x;
    int tx = tid & 15, ty = tid >> 4;
    int m0 = blockIdx.y * 128, n0 = blockIdx.x * 128;
    int kbase = blockIdx.z * nslabs * TK;
    int ar = tid >> 2, ak = (tid & 3) * 4;

    float4 av, bv4;
#define LOAD(K0) do { \
        av  = *(const float4*)(A + (long long)(m0 + ar) * HH + (K0) + ak); \
        bv4 = *(const float4*)(B + (long long)(n0 + ar) * HH + (K0) + ak); \
    } while (0)
#define STORE(BUF) do { \
        As[BUF][ak+0][ar] = av.x; As[BUF][ak+1][ar] = av.y; \
        As[BUF][ak+2][ar] = av.z; As[BUF][ak+3][ar] = av.w; \
        Bs[BUF][ak+0][ar] = bv4.x; Bs[BUF][ak+1][ar] = bv4.y; \
        Bs[BUF][ak+2][ar] = bv4.z; Bs[BUF][ak+3][ar] = bv4.w; \
    } while (0)

    float acc[4][8];
    #pragma unroll
    for (int i = 0; i < 4; i++)
        #pragma unroll
        for (int j = 0; j < 8; j++) acc[i][j] = 0.f;

    LOAD(kbase); STORE(0); __syncthreads();
    for (int kt = 0; kt < nslabs; kt++) {
        int cur = kt & 1;
        if (kt + 1 < nslabs) LOAD(kbase + (kt + 1) * TK);
        #pragma unroll
        for (int kk = 0; kk < TK; kk++) {
            float a[4], b[8];
            *(float4*)a       = *(const float4*)&As[cur][kk][ty * 4];
            *(float4*)b       = *(const float4*)&Bs[cur][kk][tx * 8];
            *(float4*)(b + 4) = *(const float4*)&Bs[cur][kk][tx * 8 + 4];
            #pragma unroll
            for (int i = 0; i < 4; i++)
                #pragma unroll
                for (int j = 0; j < 8; j++)
                    acc[i][j] = fmaf(a[i], b[j], acc[i][j]);
        }
        if (kt + 1 < nslabs) { STORE(cur ^ 1); __syncthreads(); }
    }
    #pragma unroll
    for (int i = 0; i < 4; i++)
        #pragma unroll
        for (int j = 0; j < 8; j++)
            atomicAdd(&C[(long long)(m0 + ty * 4 + i) * HH + n0 + tx * 8 + j], acc[i][j]);
#undef LOAD
#undef STORE
}

// -------- main gathered NN: u = Gk(seq) @ M; split-K=2 into two buffers ----
__global__ __launch_bounds__(512)
void nn_gather_store(const float* __restrict__ A, const float* __restrict__ B,
                     float* __restrict__ C0, float* __restrict__ C1,
                     const int* __restrict__ gidx, int nslabs) {
    __shared__ __align__(16) float As[2][TK][132];
    __shared__ __align__(16) float Bs[2][TK][128];
    __shared__ long long rowbase[128];
    int tid = threadIdx.x;
    int tx = tid & 15, ty = tid >> 4;
    int m0 = blockIdx.y * 128, c0 = blockIdx.x * 128;
    int kbase = blockIdx.z * nslabs * TK;
    float* C = blockIdx.z ? C1 : C0;

    if (tid < 128) {
        int m = m0 + tid;
        rowbase[tid] = ((long long)(m >> 7) * SS + gidx[m]) * HH;
    }
    __syncthreads();

    int ar = tid >> 2, ak = (tid & 3) * 4;
    int bkr = tid >> 5, bcc = (tid & 31) * 4;
    long long ra = rowbase[ar];

    float4 av, bv4;
#define LOAD(K0) do { \
        av  = *(const float4*)(A + ra + (K0) + ak); \
        bv4 = *(const float4*)(B + (long long)((K0) + bkr) * HH + c0 + bcc); \
    } while (0)
#define STORE(BUF) do { \
        As[BUF][ak+0][ar] = av.x; As[BUF][ak+1][ar] = av.y; \
        As[BUF][ak+2][ar] = av.z; As[BUF][ak+3][ar] = av.w; \
        *(float4*)&Bs[BUF][bkr][bcc] = bv4; \
    } while (0)

    float acc[4][8];
    #pragma unroll
    for (int i = 0; i < 4; i++)
        #pragma unroll
        for (int j = 0; j < 8; j++) acc[i][j] = 0.f;

    LOAD(kbase); STORE(0); __syncthreads();
    for (int kt = 0; kt < nslabs; kt++) {
        int cur = kt & 1;
        if (kt + 1 < nslabs) LOAD(kbase + (kt + 1) * TK);
        #pragma unroll
        for (int kk = 0; kk < TK; kk++) {
            float a[4], b[8];
            *(float4*)a       = *(const float4*)&As[cur][kk][ty * 4];
            *(float4*)b       = *(const float4*)&Bs[cur][kk][tx * 8];
            *(float4*)(b + 4) = *(const float4*)&Bs[cur][kk][tx * 8 + 4];
            #pragma unroll
            for (int i = 0; i < 4; i++)
                #pragma unroll
                for (int j = 0; j < 8; j++)
                    acc[i][j] = fmaf(a[i], b[j], acc[i][j]);
        }
        if (kt + 1 < nslabs) { STORE(cur ^ 1); __syncthreads(); }
    }
    #pragma unroll
    for (int i = 0; i < 4; i++) {
        long long r = m0 + ty * 4 + i;
        *(float4*)&C[r * HH + c0 + tx * 8]     = *(float4*)&acc[i][0];
        *(float4*)&C[r * HH + c0 + tx * 8 + 4] = *(float4*)&acc[i][4];
    }
#undef LOAD
#undef STORE
}

// ------ biaffine term1: biaf4[s][b,i,j] = u[b,i,ks] . Gv[b,j,ks] ----------
__global__ __launch_bounds__(512)
void biaf_kernel(const float* __restrict__ seq, int nslabs) {
    __shared__ __align__(16) float As[2][TK][132];
    __shared__ __align__(16) float Bs[2][TK][132];
    __shared__ long long vrowbase[128];
    int b = blockIdx.y;
    int split = blockIdx.x;
    int kbase = split * nslabs * TK;
    int tid = threadIdx.x;
    int tx = tid & 15, ty = tid >> 4;

    const float* A0 = g_tmpA + (long long)b * MC * HH;
    const float* A1 = g_tmpB + (long long)b * MC * HH;

    if (tid < 128)
        vrowbase[tid] = ((long long)b * SS + g_vidx[b * MC + tid]) * HH;
    __syncthreads();

    int ar = tid >> 2, ak = (tid & 3) * 4;
    long long vb = vrowbase[ar];

    float4 av, bv4;
#define LOAD(K0) do { \
        float4 x0 = *(const float4*)(A0 + (long long)ar * HH + (K0) + ak); \
        float4 x1 = *(const float4*)(A1 + (long long)ar * HH + (K0) + ak); \
        av.x = x0.x + x1.x; av.y = x0.y + x1.y; av.z = x0.z + x1.z; av.w = x0.w + x1.w; \
        bv4 = *(const float4*)(seq + vb + (K0) + ak); \
    } while (0)
#define STORE(BUF) do { \
        As[BUF][ak+0][ar] = av.x; As[BUF][ak+1][ar] = av.y; \
        As[BUF][ak+2][ar] = av.z; As[BUF][ak+3][ar] = av.w; \
        Bs[BUF][ak+0][ar] = bv4.x; Bs[BUF][ak+1][ar] = bv4.y; \
        Bs[BUF][ak+2][ar] = bv4.z; Bs[BUF][ak+3][ar] = bv4.w; \
    } while (0)

    float acc[4][8];
    #pragma unroll
    for (int i = 0; i < 4; i++)
        #pragma unroll
        for (int j = 0; j < 8; j++) acc[i][j] = 0.f;

    LOAD(kbase); STORE(0); __syncthreads();
    for (int kt = 0; kt < nslabs; kt++) {
        int cur = kt & 1;
        if (kt + 1 < nslabs) LOAD(kbase + (kt + 1) * TK);
        #pragma unroll
        for (int kk = 0; kk < TK; kk++) {
            float a[4], bb[8];
            *(float4*)a        = *(const float4*)&As[cur][kk][ty * 4];
            *(float4*)bb       = *(const float4*)&Bs[cur][kk][tx * 8];
            *(float4*)(bb + 4) = *(const float4*)&Bs[cur][kk][tx * 8 + 4];
            #pragma unroll
            for (int i = 0; i < 4; i++)
                #pragma unroll
                for (int j = 0; j < 8; j++)
                    acc[i][j] = fmaf(a[i], bb[j], acc[i][j]);
        }
        if (kt + 1 < nslabs) { STORE(cur ^ 1); __syncthreads(); }
    }

    float* dst = g_biaf4[split] + (long long)b * (MC * MC);
    #pragma unroll
    for (int i = 0; i < 4; i++) {
        int r = ty * 4 + i;
        *(float4*)&dst[r * MC + tx * 8]     = *(float4*)&acc[i][0];
        *(float4*)&dst[r * MC + tx * 8 + 4] = *(float4*)&acc[i][4];
    }
#undef LOAD
#undef STORE
}

// ---------------- 5) spatial features + MLP + final scores ----------------
__global__ __launch_bounds__(128)
void pair_kernel(float* __restrict__ out,
                 const float* __restrict__ Ws1, const float* __restrict__ bs1,
                 const float* __restrict__ Ws2, const float* __restrict__ bs2,
                 const float* __restrict__ Wf1, const float* __restrict__ bf1,
                 const float* __restrict__ Wf2, const float* __restrict__ bf2,
                 const float* __restrict__ bbilp) {
    __shared__ float sW1[8 * 64], sb1[64];
    __shared__ float sW2[64 * 32], sb2[32];
    __shared__ float sF1[33 * 16], sb3[16], sF2[16];
    __shared__ float sbf2, sbil, srowk;
    __shared__ float kb[4];

    int i = blockIdx.x;
    int b = blockIdx.y;
    int j = threadIdx.x;

    for (int t = j; t < 512;  t += 128) sW1[t] = Ws1[t];
    for (int t = j; t < 2048; t += 128) sW2[t] = Ws2[t];
    for (int t = j; t < 528;  t += 128) sF1[t] = Wf1[t];
    if (j < 64) sb1[j] = bs1[j];
    if (j < 32) sb2[j] = bs2[j];
    if (j < 16) { sb3[j] = bf1[j]; sF2[j] = Wf2[j]; }
    if (j == 0) { sbf2 = bf2[0]; sbil = bbilp[0]; srowk = g_rowk[b * MC + i]; }
    if (j < 4)  kb[j] = g_kbox[(b * MC + i) * 4 + j];
    __syncthreads();

    float vx1 = g_vbox[(b * MC + j) * 4 + 0];
    float vy1 = g_vbox[(b * MC + j) * 4 + 1];
    float vx2 = g_vbox[(b * MC + j) * 4 + 2];
    float vy2 = g_vbox[(b * MC + j) * 4 + 3];
    float kx1 = kb[0], ky1 = kb[1], kx2 = kb[2], ky2 = kb[3];

    float kcx = (kx1 + kx2) * 0.5f, kcy = (ky1 + ky2) * 0.5f;
    float vcx = (vx1 + vx2) * 0.5f, vcy = (vy1 + vy2) * 0.5f;
    float dx = vcx - kcx, dy = vcy - kcy;
    float dist  = sqrtf(dx * dx + dy * dy + EPSF);
    float angle = atan2f(dy, dx);
    float kh = ky2 - ky1, kw = kx2 - kx1;
    float vh = vy2 - vy1, vw = vx2 - vx1;
    float h_ov = fmaxf(fminf(ky2, vy2) - fmaxf(ky1, vy1), 0.0f);
    float h_align = h_ov / (fminf(kh, vh) + EPSF);
    float v_ov = fmaxf(fminf(kx2, vx2) - fmaxf(kx1, vx1), 0.0f);
    float v_align = v_ov / (fminf(kw, vw) + EPSF);
    float area_ratio   = (vh * vw) / (kh * kw + EPSF);
    float aspect_ratio = (vw / (vh + EPSF)) / (kw / (kh + EPSF));

    float sf[8] = { dx, dy, dist, angle, h_align, v_align, area_ratio, aspect_ratio };

    float h2[32];
    #pragma unroll
    for (int t = 0; t < 32; t++) h2[t] = sb2[t];

    for (int u = 0; u < 64; u++) {
        float h = sb1[u];
        #pragma unroll
        for (int f = 0; f < 8; f++) h = fmaf(sf[f], sW1[f * 64 + u], h);
        h = fmaxf(h, 0.0f);
        #pragma unroll
        for (int t = 0; t < 32; t++) h2[t] = fmaf(h, sW2[u * 32 + t], h2[t]);
    }

    long long bidx = (long long)b * (MC * MC) + i * MC + j;
    float biafv = g_biaf4[0][bidx] + g_biaf4[1][bidx]
                + g_biaf4[2][bidx] + g_biaf4[3][bidx]
                + srowk + g_rowv[b * MC + j] + sbil;

    float f1[16];
    #pragma unroll
    for (int t = 0; t < 16; t++) f1[t] = fmaf(biafv, sF1[t], sb3[t]);
    for (int t2 = 0; t2 < 32; t2++) {
        float hv = h2[t2];
        #pragma unroll
        for (int t = 0; t < 16; t++) f1[t] = fmaf(hv, sF1[(t2 + 1) * 16 + t], f1[t]);
    }

    float score = sbf2;
    #pragma unroll
    for (int t = 0; t < 16; t++) score = fmaf(fmaxf(f1[t], 0.0f), sF2[t], score);

    out[bidx] = score;
}

// ---------------- launch ----------------
extern "C" void kernel_launch(void* const* d_in, const int* in_sizes, int n_in,
                              void* d_out, int out_size) {
    (void)in_sizes; (void)n_in; (void)out_size;
    const float* seq    = (const float*)d_in[0];
    const float* logits = (const float*)d_in[1];
    const float* bboxes = (const float*)d_in[2];
    const int*   mask   = (const int*)  d_in[3];
    const float* Wk  = (const float*)d_in[4];
    const float* bk  = (const float*)d_in[5];
    const float* Wv  = (const float*)d_in[6];
    const float* bv  = (const float*)d_in[7];
    const float* Wbil= (const float*)d_in[8];
    const float* bbil= (const float*)d_in[9];
    const float* Ws1 = (const float*)d_in[10];
    const float* bs1 = (const float*)d_in[11];
    const float* Ws2 = (const float*)d_in[12];
    const float* bs2 = (const float*)d_in[13];
    const float* Wf1 = (const float*)d_in[14];
    const float* bf1 = (const float*)d_in[15];
    const float* Wf2 = (const float*)d_in[16];
    const float* bf2 = (const float*)d_in[17];
    float* out = (float*)d_out;

    float *pWc, *pM, *pP, *pQ, *pbc, *ptA, *ptB, *prk, *prv;
    int *pkidx, *pvidx;
    cudaGetSymbolAddress((void**)&pWc,  g_Wc);
    cudaGetSymbolAddress((void**)&pM,   g_M);
    cudaGetSymbolAddress((void**)&pP,   g_p);
    cudaGetSymbolAddress((void**)&pQ,   g_q);
    cudaGetSymbolAddress((void**)&pbc,  g_bc);
    cudaGetSymbolAddress((void**)&ptA,  g_tmpA);
    cudaGetSymbolAddress((void**)&ptB,  g_tmpB);
    cudaGetSymbolAddress((void**)&prk,  g_rowk);
    cudaGetSymbolAddress((void**)&prv,  g_rowv);
    cudaGetSymbolAddress((void**)&pkidx,g_kidx);
    cudaGetSymbolAddress((void**)&pvidx,g_vidx);

    cudaMemsetAsync(pWc, 0, (size_t)HH * HH * sizeof(float));
    cudaMemsetAsync(pM,  0, (size_t)HH * HH * sizeof(float));

    conf_kernel<<<(BB * SS + 255) / 256, 256>>>(logits, mask);
    topk_kernel<<<dim3(BB, 2), 512>>>(bboxes, out);
    bc_kernel<<<HH / 128, 128>>>(bk, Wbil);
    cdot_kernel<<<1, 256>>>(bv);                                 // c = s1.bv
    rowdot_kernel<<<(HH / 8), 256>>>(Wv, pbc, pQ);               // q = Wv @ s1

    // Wc = Wk @ Wbil (split-K x4, atomic)
    nn_atomic<<<dim3(HH / 128, HH / 128, 4), 512>>>(Wk, Wbil, pWc, 12);
    // M = Wc @ Wv^T (split-K x4, atomic)
    nt_atomic<<<dim3(HH / 128, HH / 128, 4), 512>>>(pWc, Wv, pM, 12);
    // p = Wc @ bv
    rowdot_kernel<<<(HH / 8), 256>>>(pWc, bv, pP);

    // u = Gk(seq) @ M, split-K=2 into tmpA/tmpB
    nn_gather_store<<<dim3(HH / 128, (BB * MC) / 128, 2), 512>>>(
        seq, pM, ptA, ptB, pkidx, 24);

    // rowk = Gk.p ; rowv = Gv.q + c
    growdot_kernel<<<dim3((BB * MC) / 8, 2), 256>>>(seq);

    // biaffine term1, split-K x4 into 4 buffers
    biaf_kernel<<<dim3(4, BB), 512>>>(seq, 12);

    pair_kernel<<<dim3(MC, BB), 128>>>(out, Ws1, bs1, Ws2, bs2,
                                       Wf1, bf1, Wf2, bf2, bbil);
}

// round 6
// speedup vs baseline: 1.2351x; 1.2351x over previous
#include <cuda_runtime.h>
#include <math.h>

#define BB 32
#define SS 512
#define HH 768
#define MC 128
#define EPSF 1e-8f
#define TK 16

// ---------------- scratch (static device memory; no allocs) ----------------
__device__ float g_keyconf[BB*SS];
__device__ float g_valconf[BB*SS];
__device__ int   g_kidx[BB*MC];
__device__ int   g_vidx[BB*MC];
__device__ float g_kbox[BB*MC*4];
__device__ float g_vbox[BB*MC*4];
__device__ float g_valreps[BB*MC*HH];
__device__ float g_tmp[BB*MC*HH];
__device__ float g_biaf4[4][BB*MC*MC];
__device__ float g_Wc[HH*HH];
__device__ float g_bc[HH];
__device__ float g_W2f[64*16];
__device__ float g_b2f[16];

// ---------------- 1) softmax + argmax + mask ----------------
__global__ void conf_kernel(const float* __restrict__ logits,
                            const int* __restrict__ mask) {
    int t = blockIdx.x * blockDim.x + threadIdx.x;
    if (t >= BB * SS) return;
    float l0 = logits[3*t+0], l1 = logits[3*t+1], l2 = logits[3*t+2];
    int pred = 0; float best = l0;
    if (l1 > best) { pred = 1; best = l1; }
    if (l2 > best) { pred = 2; best = l2; }
    float e0 = expf(l0 - best), e1 = expf(l1 - best), e2 = expf(l2 - best);
    float inv = 1.0f / (e0 + e1 + e2);
    bool valid = (mask[t] == 1);
    float ninf = -INFINITY;
    g_keyconf[t] = (pred == 1 && valid) ? e1 * inv : ninf;
    g_valconf[t] = (pred == 2 && valid) ? e2 * inv : ninf;
}

// ---------------- 2) exact top-128 of 512 via bitonic sort ----------------
__global__ void topk_kernel(const float* __restrict__ bboxes,
                            float* __restrict__ out) {
    int b = blockIdx.x;
    int which = blockIdx.y;   // 0 = key, 1 = val
    const float* conf = (which == 0) ? g_keyconf : g_valconf;
    __shared__ float sc[512];
    __shared__ int   si[512];
    int tid = threadIdx.x;
    sc[tid] = conf[b * SS + tid];
    si[tid] = tid;

    for (int k = 2; k <= 512; k <<= 1) {
        for (int j = k >> 1; j > 0; j >>= 1) {
            __syncthreads();
            int ixj = tid ^ j;
            if (ixj > tid) {
                float c1 = sc[tid], c2 = sc[ixj];
                int   i1 = si[tid], i2 = si[ixj];
                bool b2 = (c2 > c1) || (c2 == c1 && i2 < i1);
                bool doswap = ((tid & k) == 0) ? b2 : !b2;
                if (doswap) {
                    sc[tid] = c2; si[tid] = i2;
                    sc[ixj] = c1; si[ixj] = i1;
                }
            }
        }
    }
    __syncthreads();

    if (tid < MC) {
        int   idx = si[tid];
        float cf  = sc[tid];
        int*   gi = (which == 0) ? g_kidx : g_vidx;
        float* gb = (which == 0) ? g_kbox : g_vbox;
        gi[b * MC + tid] = idx;
        const float* src = bboxes + ((long long)b * SS + idx) * 4;
        float* dst = gb + (b * MC + tid) * 4;
        dst[0] = src[0]; dst[1] = src[1]; dst[2] = src[2]; dst[3] = src[3];
        long long base = (long long)BB * MC * MC;            // 524288
        float vf = (cf != -INFINITY) ? 1.0f : 0.0f;
        out[base + (long long)which * (BB * MC) + b * MC + tid] = vf;
        out[base + 2LL * (BB * MC) + (long long)which * (BB * MC) + b * MC + tid] = (float)idx;
    }
}

// ---------------- bc[j] = sum_h bk[h] * Wbil[h,j] ----------------
__global__ void bc_kernel(const float* __restrict__ bk,
                          const float* __restrict__ Wbil) {
    int j = blockIdx.x * 128 + threadIdx.x;
    float s = 0.0f;
    for (int h = 0; h < HH; h++) s = fmaf(bk[h], Wbil[h * HH + j], s);
    g_bc[j] = s;
}

// ---------------- fold: W2f = Ws2 @ Wf1[1:33], b2f = bs2@Wf1[1:] + bf1 ----
__global__ void fold_kernel(const float* __restrict__ Ws2,
                            const float* __restrict__ bs2,
                            const float* __restrict__ Wf1,
                            const float* __restrict__ bf1) {
    int tid = threadIdx.x;
    #pragma unroll
    for (int e = 0; e < 4; e++) {
        int o = tid * 4 + e;
        if (o < 1024) {
            int u = o >> 4, t = o & 15;
            float s = 0.f;
            #pragma unroll
            for (int s2 = 0; s2 < 32; s2++)
                s = fmaf(Ws2[u * 32 + s2], Wf1[(s2 + 1) * 16 + t], s);
            g_W2f[o] = s;
        }
    }
    if (tid < 16) {
        float s = bf1[tid];
        #pragma unroll
        for (int s2 = 0; s2 < 32; s2++)
            s = fmaf(bs2[s2], Wf1[(s2 + 1) * 16 + tid], s);
        g_b2f[tid] = s;
    }
}

// ---------------- 3a) Wc = Wk @ Wbil, split-K x8, 512 threads, atomic -----
__global__ __launch_bounds__(512)
void wc_splitk(const float* __restrict__ A, const float* __restrict__ B) {
    __shared__ __align__(16) float As[2][TK][132];
    __shared__ __align__(16) float Bs[2][TK][128];
    const int nslabs = 6;                      // 96 K per split
    int tid = threadIdx.x;
    int tx = tid & 15, ty = tid >> 4;
    int m0 = blockIdx.y * 128, c0 = blockIdx.x * 128;
    int kbase = blockIdx.z * nslabs * TK;
    int ar = tid >> 2, ak = (tid & 3) * 4;
    int bkr = tid >> 5, bcc = (tid & 31) * 4;

    float4 av, bv4;
#define LOAD(K0) do { \
        av  = *(const float4*)(A + (long long)(m0 + ar) * HH + (K0) + ak); \
        bv4 = *(const float4*)(B + (long long)((K0) + bkr) * HH + c0 + bcc); \
    } while (0)
#define STORE(BUF) do { \
        As[BUF][ak+0][ar] = av.x; As[BUF][ak+1][ar] = av.y; \
        As[BUF][ak+2][ar] = av.z; As[BUF][ak+3][ar] = av.w; \
        *(float4*)&Bs[BUF][bkr][bcc] = bv4; \
    } while (0)

    float acc[4][8];
    #pragma unroll
    for (int i = 0; i < 4; i++)
        #pragma unroll
        for (int j = 0; j < 8; j++) acc[i][j] = 0.f;

    LOAD(kbase); STORE(0); __syncthreads();
    for (int kt = 0; kt < nslabs; kt++) {
        int cur = kt & 1;
        if (kt + 1 < nslabs) LOAD(kbase + (kt + 1) * TK);
        #pragma unroll
        for (int kk = 0; kk < TK; kk++) {
            float a[4], b[8];
            *(float4*)a       = *(const float4*)&As[cur][kk][ty * 4];
            *(float4*)b       = *(const float4*)&Bs[cur][kk][tx * 8];
            *(float4*)(b + 4) = *(const float4*)&Bs[cur][kk][tx * 8 + 4];
            #pragma unroll
            for (int i = 0; i < 4; i++)
                #pragma unroll
                for (int j = 0; j < 8; j++)
                    acc[i][j] = fmaf(a[i], b[j], acc[i][j]);
        }
        if (kt + 1 < nslabs) { STORE(cur ^ 1); __syncthreads(); }
    }
    #pragma unroll
    for (int i = 0; i < 4; i++)
        #pragma unroll
        for (int j = 0; j < 8; j++)
            atomicAdd(&g_Wc[(long long)(m0 + ty * 4 + i) * HH + c0 + tx * 8 + j],
                      acc[i][j]);
#undef LOAD
#undef STORE
}

// ---------------- 3b) main gathered SGEMM: 128x128 tile, 8x8, scalar ------
__global__ __launch_bounds__(256)
void sgemm128(const float* __restrict__ A0, const float* __restrict__ B0,
              const float* __restrict__ bias0, float* __restrict__ C0, const int* __restrict__ g0,
              const float* __restrict__ A1, const float* __restrict__ B1,
              const float* __restrict__ bias1, float* __restrict__ C1, const int* __restrict__ g1) {
    __shared__ __align__(16) float As[2][TK][132];
    __shared__ __align__(16) float Bs[2][TK][128];
    __shared__ long long rowbase[128];

    const float* A; const float* Bm; const float* bias; float* C; const int* gidx;
    if (blockIdx.z == 0) { A = A0; Bm = B0; bias = bias0; C = C0; gidx = g0; }
    else                 { A = A1; Bm = B1; bias = bias1; C = C1; gidx = g1; }

    int tid = threadIdx.x;
    int tx = tid & 15, ty = tid >> 4;
    int m0 = blockIdx.y * 128, c0 = blockIdx.x * 128;

    if (tid < 128) {
        int m = m0 + tid;
        int b = m >> 7;
        rowbase[tid] = ((long long)b * SS + gidx[m]) * HH;
    }
    __syncthreads();

    int ar0 = tid >> 2, ak0 = (tid & 3) * 4, ar1 = ar0 + 64;
    int bk0 = tid >> 5, bc0 = (tid & 31) * 4, bk1 = bk0 + 8;
    long long ra0 = rowbase[ar0];
    long long ra1 = rowbase[ar1];

    float4 a0v, a1v, b0v, b1v;
#define LOAD_REGS(K0) do { \
        a0v = *(const float4*)(A + ra0 + (K0) + ak0); \
        a1v = *(const float4*)(A + ra1 + (K0) + ak0); \
        b0v = *(const float4*)(Bm + (long long)((K0) + bk0) * HH + c0 + bc0); \
        b1v = *(const float4*)(Bm + (long long)((K0) + bk1) * HH + c0 + bc0); \
    } while (0)
#define STORE_SMEM(BUF) do { \
        As[BUF][ak0+0][ar0] = a0v.x; As[BUF][ak0+1][ar0] = a0v.y; \
        As[BUF][ak0+2][ar0] = a0v.z; As[BUF][ak0+3][ar0] = a0v.w; \
        As[BUF][ak0+0][ar1] = a1v.x; As[BUF][ak0+1][ar1] = a1v.y; \
        As[BUF][ak0+2][ar1] = a1v.z; As[BUF][ak0+3][ar1] = a1v.w; \
        *(float4*)&Bs[BUF][bk0][bc0] = b0v; \
        *(float4*)&Bs[BUF][bk1][bc0] = b1v; \
    } while (0)

    float acc[8][8];
    #pragma unroll
    for (int i = 0; i < 8; i++)
        #pragma unroll
        for (int j = 0; j < 8; j++) acc[i][j] = 0.0f;

    LOAD_REGS(0);
    STORE_SMEM(0);
    __syncthreads();

    const int NT = HH / TK;   // 48
    for (int kt = 0; kt < NT; kt++) {
        int cur = kt & 1;
        if (kt + 1 < NT) LOAD_REGS((kt + 1) * TK);
        #pragma unroll
        for (int kk = 0; kk < TK; kk++) {
            float a[8], b[8];
            *(float4*)(a)     = *(const float4*)&As[cur][kk][ty * 8];
            *(float4*)(a + 4) = *(const float4*)&As[cur][kk][ty * 8 + 4];
            *(float4*)(b)     = *(const float4*)&Bs[cur][kk][tx * 8];
            *(float4*)(b + 4) = *(const float4*)&Bs[cur][kk][tx * 8 + 4];
            #pragma unroll
            for (int i = 0; i < 8; i++)
                #pragma unroll
                for (int j = 0; j < 8; j++)
                    acc[i][j] = fmaf(a[i], b[j], acc[i][j]);
        }
        if (kt + 1 < NT) { STORE_SMEM(cur ^ 1); __syncthreads(); }
    }

    float bv8[8];
    #pragma unroll
    for (int j = 0; j < 8; j++) bv8[j] = bias[c0 + tx * 8 + j];

    #pragma unroll
    for (int i = 0; i < 8; i++) {
        int r = m0 + ty * 8 + i;
        float4 v0, v1;
        v0.x = acc[i][0] + bv8[0]; v0.y = acc[i][1] + bv8[1];
        v0.z = acc[i][2] + bv8[2]; v0.w = acc[i][3] + bv8[3];
        v1.x = acc[i][4] + bv8[4]; v1.y = acc[i][5] + bv8[5];
        v1.z = acc[i][6] + bv8[6]; v1.w = acc[i][7] + bv8[7];
        *(float4*)&C[(long long)r * HH + c0 + tx * 8]     = v0;
        *(float4*)&C[(long long)r * HH + c0 + tx * 8 + 4] = v1;
    }
#undef LOAD_REGS
#undef STORE_SMEM
}

// ------- 4) biaffine split-K x4 into 4 buffers, 512 threads, no atomics ---
__global__ __launch_bounds__(512)
void biaf_splitk() {
    __shared__ __align__(16) float As[2][TK][132];
    __shared__ __align__(16) float Bs[2][TK][132];
    const int nslabs = 12;                  // 192 K per split
    int b = blockIdx.y;
    int split = blockIdx.x;
    int kbase = split * nslabs * TK;
    int tid = threadIdx.x;
    int tx = tid & 15, ty = tid >> 4;

    const float* A = g_tmp     + (long long)b * MC * HH;
    const float* V = g_valreps + (long long)b * MC * HH;

    int ar = tid >> 2, ak = (tid & 3) * 4;

    float4 av, bv4;
#define LOAD(K0) do { \
        av  = *(const float4*)(A + (long long)ar * HH + (K0) + ak); \
        bv4 = *(const float4*)(V + (long long)ar * HH + (K0) + ak); \
    } while (0)
#define STORE(BUF) do { \
        As[BUF][ak+0][ar] = av.x; As[BUF][ak+1][ar] = av.y; \
        As[BUF][ak+2][ar] = av.z; As[BUF][ak+3][ar] = av.w; \
        Bs[BUF][ak+0][ar] = bv4.x; Bs[BUF][ak+1][ar] = bv4.y; \
        Bs[BUF][ak+2][ar] = bv4.z; Bs[BUF][ak+3][ar] = bv4.w; \
    } while (0)

    float acc[4][8];
    #pragma unroll
    for (int i = 0; i < 4; i++)
        #pragma unroll
        for (int j = 0; j < 8; j++) acc[i][j] = 0.f;

    LOAD(kbase); STORE(0); __syncthreads();
    for (int kt = 0; kt < nslabs; kt++) {
        int cur = kt & 1;
        if (kt + 1 < nslabs) LOAD(kbase + (kt + 1) * TK);
        #pragma unroll
        for (int kk = 0; kk < TK; kk++) {
            float a[4], bb[8];
            *(float4*)a        = *(const float4*)&As[cur][kk][ty * 4];
            *(float4*)bb       = *(const float4*)&Bs[cur][kk][tx * 8];
            *(float4*)(bb + 4) = *(const float4*)&Bs[cur][kk][tx * 8 + 4];
            #pragma unroll
            for (int i = 0; i < 4; i++)
                #pragma unroll
                for (int j = 0; j < 8; j++)
                    acc[i][j] = fmaf(a[i], bb[j], acc[i][j]);
        }
        if (kt + 1 < nslabs) { STORE(cur ^ 1); __syncthreads(); }
    }

    float* dst = g_biaf4[split] + (long long)b * (MC * MC);
    #pragma unroll
    for (int i = 0; i < 4; i++) {
        int r = ty * 4 + i;
        *(float4*)&dst[r * MC + tx * 8]     = *(float4*)&acc[i][0];
        *(float4*)&dst[r * MC + tx * 8 + 4] = *(float4*)&acc[i][4];
    }
#undef LOAD
#undef STORE
}

// ---------------- 5) spatial features + folded MLP + final scores ---------
__global__ __launch_bounds__(128)
void pair_kernel(float* __restrict__ out,
                 const float* __restrict__ Ws1, const float* __restrict__ bs1,
                 const float* __restrict__ Wf1,
                 const float* __restrict__ Wf2, const float* __restrict__ bf2,
                 const float* __restrict__ bbilp) {
    __shared__ float sW1[8 * 64], sb1[64];
    __shared__ float sW2f[64 * 16], sb2f[16];
    __shared__ float sF0[16], sF2[16];
    __shared__ float sbf2, sbil;
    __shared__ float kb[4];

    int i = blockIdx.x;
    int b = blockIdx.y;
    int j = threadIdx.x;

    for (int t = j; t < 512;  t += 128) sW1[t] = Ws1[t];
    for (int t = j; t < 1024; t += 128) sW2f[t] = g_W2f[t];
    if (j < 64) sb1[j] = bs1[j];
    if (j < 16) { sb2f[j] = g_b2f[j]; sF0[j] = Wf1[j]; sF2[j] = Wf2[j]; }
    if (j == 0) { sbf2 = bf2[0]; sbil = bbilp[0]; }
    if (j < 4)  kb[j] = g_kbox[(b * MC + i) * 4 + j];
    __syncthreads();

    float vx1 = g_vbox[(b * MC + j) * 4 + 0];
    float vy1 = g_vbox[(b * MC + j) * 4 + 1];
    float vx2 = g_vbox[(b * MC + j) * 4 + 2];
    float vy2 = g_vbox[(b * MC + j) * 4 + 3];
    float kx1 = kb[0], ky1 = kb[1], kx2 = kb[2], ky2 = kb[3];

    float kcx = (kx1 + kx2) * 0.5f, kcy = (ky1 + ky2) * 0.5f;
    float vcx = (vx1 + vx2) * 0.5f, vcy = (vy1 + vy2) * 0.5f;
    float dx = vcx - kcx, dy = vcy - kcy;
    float dist  = sqrtf(dx * dx + dy * dy + EPSF);
    float angle = atan2f(dy, dx);
    float kh = ky2 - ky1, kw = kx2 - kx1;
    float vh = vy2 - vy1, vw = vx2 - vx1;
    float h_ov = fmaxf(fminf(ky2, vy2) - fmaxf(ky1, vy1), 0.0f);
    float h_align = h_ov / (fminf(kh, vh) + EPSF);
    float v_ov = fmaxf(fminf(kx2, vx2) - fmaxf(kx1, vx1), 0.0f);
    float v_align = v_ov / (fminf(kw, vw) + EPSF);
    float area_ratio   = (vh * vw) / (kh * kw + EPSF);
    float aspect_ratio = (vw / (vh + EPSF)) / (kw / (kh + EPSF));

    float sf[8] = { dx, dy, dist, angle, h_align, v_align, area_ratio, aspect_ratio };

    long long bidx = (long long)b * (MC * MC) + i * MC + j;
    float biafv = g_biaf4[0][bidx] + g_biaf4[1][bidx]
                + g_biaf4[2][bidx] + g_biaf4[3][bidx] + sbil;

    float f1[16];
    #pragma unroll
    for (int t = 0; t < 16; t++) f1[t] = fmaf(biafv, sF0[t], sb2f[t]);

    for (int u = 0; u < 64; u++) {
        float h = sb1[u];
        #pragma unroll
        for (int f = 0; f < 8; f++) h = fmaf(sf[f], sW1[f * 64 + u], h);
        h = fmaxf(h, 0.0f);
        #pragma unroll
        for (int t = 0; t < 16; t++) f1[t] = fmaf(h, sW2f[u * 16 + t], f1[t]);
    }

    float score = sbf2;
    #pragma unroll
    for (int t = 0; t < 16; t++) score = fmaf(fmaxf(f1[t], 0.0f), sF2[t], score);

    out[bidx] = score;
}

// ---------------- launch ----------------
extern "C" void kernel_launch(void* const* d_in, const int* in_sizes, int n_in,
                              void* d_out, int out_size) {
    (void)in_sizes; (void)n_in; (void)out_size;
    const float* seq    = (const float*)d_in[0];
    const float* logits = (const float*)d_in[1];
    const float* bboxes = (const float*)d_in[2];
    const int*   mask   = (const int*)  d_in[3];
    const float* Wk  = (const float*)d_in[4];
    const float* bk  = (const float*)d_in[5];
    const float* Wv  = (const float*)d_in[6];
    const float* bv  = (const float*)d_in[7];
    const float* Wbil= (const float*)d_in[8];
    const float* bbil= (const float*)d_in[9];
    const float* Ws1 = (const float*)d_in[10];
    const float* bs1 = (const float*)d_in[11];
    const float* Ws2 = (const float*)d_in[12];
    const float* bs2 = (const float*)d_in[13];
    const float* Wf1 = (const float*)d_in[14];
    const float* bf1 = (const float*)d_in[15];
    const float* Wf2 = (const float*)d_in[16];
    const float* bf2 = (const float*)d_in[17];
    float* out = (float*)d_out;

    float *pWc, *pbc, *pvrep, *ptmp; int *pkidx, *pvidx;
    cudaGetSymbolAddress((void**)&pWc,  g_Wc);
    cudaGetSymbolAddress((void**)&pbc,  g_bc);
    cudaGetSymbolAddress((void**)&pvrep,g_valreps);
    cudaGetSymbolAddress((void**)&ptmp, g_tmp);
    cudaGetSymbolAddress((void**)&pkidx,g_kidx);
    cudaGetSymbolAddress((void**)&pvidx,g_vidx);

    cudaMemsetAsync(pWc, 0, (size_t)HH * HH * sizeof(float));

    conf_kernel<<<(BB * SS + 255) / 256, 256>>>(logits, mask);
    topk_kernel<<<dim3(BB, 2), 512>>>(bboxes, out);
    bc_kernel<<<HH / 128, 128>>>(bk, Wbil);
    fold_kernel<<<1, 256>>>(Ws2, bs2, Wf1, bf1);

    // Wc = Wk @ Wbil, split-K x8 (288 blocks, 512 threads)
    wc_splitk<<<dim3(HH / 128, HH / 128, 8), 512>>>(Wk, Wbil);

    // z=0: val_reps = gather_v(seq) @ Wv + bv
    // z=1: tmp      = gather_k(seq) @ Wc + bc
    sgemm128<<<dim3(HH / 128, (BB * MC) / 128, 2), 256>>>(
        seq, Wv,  bv,  pvrep, pvidx,
        seq, pWc, pbc, ptmp,  pkidx);

    // biaffine split-K x4 into 4 buffers (128 blocks, 512 threads)
    biaf_splitk<<<dim3(4, BB), 512>>>();

    pair_kernel<<<dim3(MC, BB), 128>>>(out, Ws1, bs1, Wf1, Wf2, bf2, bbil);
}

// round 7
// speedup vs baseline: 1.3839x; 1.1205x over previous
#include <cuda_runtime.h>
#include <math.h>

#define BB 32
#define SS 512
#define HH 768
#define MC 128
#define EPSF 1e-8f
#define TK 16

// ---------------- scratch (static device memory; no allocs) ----------------
__device__ int   g_kidx[BB*MC];
__device__ int   g_vidx[BB*MC];
__device__ float g_kbox[BB*MC*4];
__device__ float g_vbox[BB*MC*4];
__device__ float g_u[BB*MC*HH];
__device__ float g_biaf4[4][BB*MC*MC];
__device__ float g_Wc2[HH*HH];   // Wbil @ Wv^T
__device__ float g_M[HH*HH];     // Wk @ Wc2
__device__ float g_s1[HH];       // bk @ Wbil
__device__ float g_r[HH];        // Wbil @ bv
__device__ float g_q[HH];        // Wv @ s1
__device__ float g_p[HH];        // Wk @ r
__device__ float g_c[1];         // s1 . bv
__device__ float g_rowk[BB*MC];
__device__ float g_rowv[BB*MC];
__device__ float g_W2f[64*16];
__device__ float g_b2f[16];

// -------- 1+2) conf (inline) + exact top-128 of 512 via bitonic sort ------
__global__ void topk_kernel(const float* __restrict__ logits,
                            const int* __restrict__ mask,
                            const float* __restrict__ bboxes,
                            float* __restrict__ out) {
    int b = blockIdx.x;
    int which = blockIdx.y;   // 0 = key, 1 = val
    __shared__ float sc[512];
    __shared__ int   si[512];
    int tid = threadIdx.x;

    {   // inline confidence
        int t = b * SS + tid;
        float l0 = logits[3*t+0], l1 = logits[3*t+1], l2 = logits[3*t+2];
        int pred = 0; float best = l0;
        if (l1 > best) { pred = 1; best = l1; }
        if (l2 > best) { pred = 2; best = l2; }
        float e0 = expf(l0 - best), e1 = expf(l1 - best), e2 = expf(l2 - best);
        float inv = 1.0f / (e0 + e1 + e2);
        bool valid = (mask[t] == 1);
        float conf;
        if (which == 0) conf = (pred == 1 && valid) ? e1 * inv : -INFINITY;
        else            conf = (pred == 2 && valid) ? e2 * inv : -INFINITY;
        sc[tid] = conf; si[tid] = tid;
    }

    for (int k = 2; k <= 512; k <<= 1) {
        for (int j = k >> 1; j > 0; j >>= 1) {
            __syncthreads();
            int ixj = tid ^ j;
            if (ixj > tid) {
                float c1 = sc[tid], c2 = sc[ixj];
                int   i1 = si[tid], i2 = si[ixj];
                bool b2 = (c2 > c1) || (c2 == c1 && i2 < i1);
                bool doswap = ((tid & k) == 0) ? b2 : !b2;
                if (doswap) {
                    sc[tid] = c2; si[tid] = i2;
                    sc[ixj] = c1; si[ixj] = i1;
                }
            }
        }
    }
    __syncthreads();

    if (tid < MC) {
        int   idx = si[tid];
        float cf  = sc[tid];
        int*   gi = (which == 0) ? g_kidx : g_vidx;
        float* gb = (which == 0) ? g_kbox : g_vbox;
        gi[b * MC + tid] = idx;
        const float* src = bboxes + ((long long)b * SS + idx) * 4;
        float* dst = gb + (b * MC + tid) * 4;
        dst[0] = src[0]; dst[1] = src[1]; dst[2] = src[2]; dst[3] = src[3];
        long long base = (long long)BB * MC * MC;            // 524288
        float vf = (cf != -INFINITY) ? 1.0f : 0.0f;
        out[base + (long long)which * (BB * MC) + b * MC + tid] = vf;
        out[base + 2LL * (BB * MC) + (long long)which * (BB * MC) + b * MC + tid] = (float)idx;
    }
}

// ---------------- setupA: s1 = bk @ Wbil ; r = Wbil @ bv -------------------
__global__ void setupA(const float* __restrict__ bk,
                       const float* __restrict__ Wbil,
                       const float* __restrict__ bv) {
    int bx = blockIdx.x, tid = threadIdx.x;
    if (bx < 3) {                 // s1: column dots, thread per output
        int j = bx * 256 + tid;
        float s = 0.f;
        for (int h = 0; h < HH; h++) s = fmaf(bk[h], Wbil[h * HH + j], s);
        g_s1[j] = s;
    } else {                      // r: row dots, warp per row
        int row = (bx - 3) * 8 + (tid >> 5);
        int lane = tid & 31;
        const float* rp = Wbil + (long long)row * HH;
        float s = 0.f;
        #pragma unroll 4
        for (int cdx = lane; cdx < HH; cdx += 32) s = fmaf(rp[cdx], bv[cdx], s);
        #pragma unroll
        for (int o = 16; o; o >>= 1) s += __shfl_xor_sync(0xffffffffu, s, o);
        if (lane == 0) g_r[row] = s;
    }
}

// -------- setupB: q = Wv@s1 ; p = Wk@r ; c = s1.bv ; MLP fold --------------
__global__ void setupB(const float* __restrict__ Wv, const float* __restrict__ Wk,
                       const float* __restrict__ bv,
                       const float* __restrict__ Ws2, const float* __restrict__ bs2,
                       const float* __restrict__ Wf1, const float* __restrict__ bf1) {
    int bx = blockIdx.x, tid = threadIdx.x;
    if (bx < 192) {               // warp-per-row dots
        const float* A   = (bx < 96) ? Wv : Wk;
        const float* x   = (bx < 96) ? g_s1 : g_r;
        float* outv      = (bx < 96) ? g_q : g_p;
        int row = ((bx < 96) ? bx : bx - 96) * 8 + (tid >> 5);
        int lane = tid & 31;
        const float* rp = A + (long long)row * HH;
        float s = 0.f;
        #pragma unroll 4
        for (int cdx = lane; cdx < HH; cdx += 32) s = fmaf(rp[cdx], x[cdx], s);
        #pragma unroll
        for (int o = 16; o; o >>= 1) s += __shfl_xor_sync(0xffffffffu, s, o);
        if (lane == 0) outv[row] = s;
    } else {                      // fold + c
        #pragma unroll
        for (int e = 0; e < 4; e++) {
            int o = tid * 4 + e;
            if (o < 1024) {
                int u = o >> 4, t = o & 15;
                float s = 0.f;
                #pragma unroll
                for (int s2 = 0; s2 < 32; s2++)
                    s = fmaf(Ws2[u * 32 + s2], Wf1[(s2 + 1) * 16 + t], s);
                g_W2f[o] = s;
            }
        }
        if (tid < 16) {
            float s = bf1[tid];
            #pragma unroll
            for (int s2 = 0; s2 < 32; s2++)
                s = fmaf(bs2[s2], Wf1[(s2 + 1) * 16 + tid], s);
            g_b2f[tid] = s;
        }
        __shared__ float red[256];
        float s = 0.f;
        for (int g = tid; g < HH; g += 256) s = fmaf(g_s1[g], bv[g], s);
        red[tid] = s; __syncthreads();
        for (int o = 128; o; o >>= 1) { if (tid < o) red[tid] += red[tid + o]; __syncthreads(); }
        if (tid == 0) g_c[0] = red[0];
    }
}

// ---------------- NT split-K atomic: Wc2 = Wbil @ Wv^T ---------------------
__global__ __launch_bounds__(512)
void nt_atomic(const float* __restrict__ A, const float* __restrict__ B,
               float* __restrict__ C) {
    __shared__ __align__(16) float As[2][TK][132];
    __shared__ __align__(16) float Bs[2][TK][132];
    const int nslabs = 12;
    int tid = threadIdx.x;
    int tx = tid & 15, ty = tid >> 4;
    int m0 = blockIdx.y * 128, n0 = blockIdx.x * 128;
    int kbase = blockIdx.z * nslabs * TK;
    int ar = tid >> 2, ak = (tid & 3) * 4;

    float4 av, bv4;
#define LOAD(K0) do { \
        av  = *(const float4*)(A + (long long)(m0 + ar) * HH + (K0) + ak); \
        bv4 = *(const float4*)(B + (long long)(n0 + ar) * HH + (K0) + ak); \
    } while (0)
#define STORE(BUF) do { \
        As[BUF][ak+0][ar] = av.x; As[BUF][ak+1][ar] = av.y; \
        As[BUF][ak+2][ar] = av.z; As[BUF][ak+3][ar] = av.w; \
        Bs[BUF][ak+0][ar] = bv4.x; Bs[BUF][ak+1][ar] = bv4.y; \
        Bs[BUF][ak+2][ar] = bv4.z; Bs[BUF][ak+3][ar] = bv4.w; \
    } while (0)

    float acc[4][8];
    #pragma unroll
    for (int i = 0; i < 4; i++)
        #pragma unroll
        for (int j = 0; j < 8; j++) acc[i][j] = 0.f;

    LOAD(kbase); STORE(0); __syncthreads();
    for (int kt = 0; kt < nslabs; kt++) {
        int cur = kt & 1;
        if (kt + 1 < nslabs) LOAD(kbase + (kt + 1) * TK);
        #pragma unroll
        for (int kk = 0; kk < TK; kk++) {
            float a[4], b[8];
            *(float4*)a       = *(const float4*)&As[cur][kk][ty * 4];
            *(float4*)b       = *(const float4*)&Bs[cur][kk][tx * 8];
            *(float4*)(b + 4) = *(const float4*)&Bs[cur][kk][tx * 8 + 4];
            #pragma unroll
            for (int i = 0; i < 4; i++)
                #pragma unroll
                for (int j = 0; j < 8; j++)
                    acc[i][j] = fmaf(a[i], b[j], acc[i][j]);
        }
        if (kt + 1 < nslabs) { STORE(cur ^ 1); __syncthreads(); }
    }
    #pragma unroll
    for (int i = 0; i < 4; i++)
        #pragma unroll
        for (int j = 0; j < 8; j++)
            atomicAdd(&C[(long long)(m0 + ty * 4 + i) * HH + n0 + tx * 8 + j], acc[i][j]);
#undef LOAD
#undef STORE
}

// ---------------- NN split-K atomic: M = Wk @ Wc2 --------------------------
__global__ __launch_bounds__(512)
void nn_atomic(const float* __restrict__ A, const float* __restrict__ B,
               float* __restrict__ C) {
    __shared__ __align__(16) float As[2][TK][132];
    __shared__ __align__(16) float Bs[2][TK][128];
    const int nslabs = 12;
    int tid = threadIdx.x;
    int tx = tid & 15, ty = tid >> 4;
    int m0 = blockIdx.y * 128, c0 = blockIdx.x * 128;
    int kbase = blockIdx.z * nslabs * TK;
    int ar = tid >> 2, ak = (tid & 3) * 4;
    int bkr = tid >> 5, bcc = (tid & 31) * 4;

    float4 av, bv4;
#define LOAD(K0) do { \
        av  = *(const float4*)(A + (long long)(m0 + ar) * HH + (K0) + ak); \
        bv4 = *(const float4*)(B + (long long)((K0) + bkr) * HH + c0 + bcc); \
    } while (0)
#define STORE(BUF) do { \
        As[BUF][ak+0][ar] = av.x; As[BUF][ak+1][ar] = av.y; \
        As[BUF][ak+2][ar] = av.z; As[BUF][ak+3][ar] = av.w; \
        *(float4*)&Bs[BUF][bkr][bcc] = bv4; \
    } while (0)

    float acc[4][8];
    #pragma unroll
    for (int i = 0; i < 4; i++)
        #pragma unroll
        for (int j = 0; j < 8; j++) acc[i][j] = 0.f;

    LOAD(kbase); STORE(0); __syncthreads();
    for (int kt = 0; kt < nslabs; kt++) {
        int cur = kt & 1;
        if (kt + 1 < nslabs) LOAD(kbase + (kt + 1) * TK);
        #pragma unroll
        for (int kk = 0; kk < TK; kk++) {
            float a[4], b[8];
            *(float4*)a       = *(const float4*)&As[cur][kk][ty * 4];
            *(float4*)b       = *(const float4*)&Bs[cur][kk][tx * 8];
            *(float4*)(b + 4) = *(const float4*)&Bs[cur][kk][tx * 8 + 4];
            #pragma unroll
            for (int i = 0; i < 4; i++)
                #pragma unroll
                for (int j = 0; j < 8; j++)
                    acc[i][j] = fmaf(a[i], b[j], acc[i][j]);
        }
        if (kt + 1 < nslabs) { STORE(cur ^ 1); __syncthreads(); }
    }
    #pragma unroll
    for (int i = 0; i < 4; i++)
        #pragma unroll
        for (int j = 0; j < 8; j++)
            atomicAdd(&C[(long long)(m0 + ty * 4 + i) * HH + c0 + tx * 8 + j], acc[i][j]);
#undef LOAD
#undef STORE
}

// --------- u = Gk(seq) @ M : full-K gathered NN, 128x128 tile, 8x8 --------
__global__ __launch_bounds__(256)
void u_gemm(const float* __restrict__ A, const float* __restrict__ Bm) {
    __shared__ __align__(16) float As[2][TK][132];
    __shared__ __align__(16) float Bs[2][TK][128];
    __shared__ long long rowbase[128];

    int tid = threadIdx.x;
    int tx = tid & 15, ty = tid >> 4;
    int m0 = blockIdx.y * 128, c0 = blockIdx.x * 128;

    if (tid < 128) {
        int m = m0 + tid;
        rowbase[tid] = ((long long)(m >> 7) * SS + g_kidx[m]) * HH;
    }
    __syncthreads();

    int ar0 = tid >> 2, ak0 = (tid & 3) * 4, ar1 = ar0 + 64;
    int bk0 = tid >> 5, bc0 = (tid & 31) * 4, bk1 = bk0 + 8;
    long long ra0 = rowbase[ar0];
    long long ra1 = rowbase[ar1];

    float4 a0v, a1v, b0v, b1v;
#define LOAD_REGS(K0) do { \
        a0v = *(const float4*)(A + ra0 + (K0) + ak0); \
        a1v = *(const float4*)(A + ra1 + (K0) + ak0); \
        b0v = *(const float4*)(Bm + (long long)((K0) + bk0) * HH + c0 + bc0); \
        b1v = *(const float4*)(Bm + (long long)((K0) + bk1) * HH + c0 + bc0); \
    } while (0)
#define STORE_SMEM(BUF) do { \
        As[BUF][ak0+0][ar0] = a0v.x; As[BUF][ak0+1][ar0] = a0v.y; \
        As[BUF][ak0+2][ar0] = a0v.z; As[BUF][ak0+3][ar0] = a0v.w; \
        As[BUF][ak0+0][ar1] = a1v.x; As[BUF][ak0+1][ar1] = a1v.y; \
        As[BUF][ak0+2][ar1] = a1v.z; As[BUF][ak0+3][ar1] = a1v.w; \
        *(float4*)&Bs[BUF][bk0][bc0] = b0v; \
        *(float4*)&Bs[BUF][bk1][bc0] = b1v; \
    } while (0)

    float acc[8][8];
    #pragma unroll
    for (int i = 0; i < 8; i++)
        #pragma unroll
        for (int j = 0; j < 8; j++) acc[i][j] = 0.0f;

    LOAD_REGS(0);
    STORE_SMEM(0);
    __syncthreads();

    const int NT = HH / TK;   // 48
    for (int kt = 0; kt < NT; kt++) {
        int cur = kt & 1;
        if (kt + 1 < NT) LOAD_REGS((kt + 1) * TK);
        #pragma unroll
        for (int kk = 0; kk < TK; kk++) {
            float a[8], b[8];
            *(float4*)(a)     = *(const float4*)&As[cur][kk][ty * 8];
            *(float4*)(a + 4) = *(const float4*)&As[cur][kk][ty * 8 + 4];
            *(float4*)(b)     = *(const float4*)&Bs[cur][kk][tx * 8];
            *(float4*)(b + 4) = *(const float4*)&Bs[cur][kk][tx * 8 + 4];
            #pragma unroll
            for (int i = 0; i < 8; i++)
                #pragma unroll
                for (int j = 0; j < 8; j++)
                    acc[i][j] = fmaf(a[i], b[j], acc[i][j]);
        }
        if (kt + 1 < NT) { STORE_SMEM(cur ^ 1); __syncthreads(); }
    }

    #pragma unroll
    for (int i = 0; i < 8; i++) {
        long long r = m0 + ty * 8 + i;
        *(float4*)&g_u[r * HH + c0 + tx * 8]     = *(float4*)&acc[i][0];
        *(float4*)&g_u[r * HH + c0 + tx * 8 + 4] = *(float4*)&acc[i][4];
    }
#undef LOAD_REGS
#undef STORE_SMEM
}

// -------- rowk = Gk.p ; rowv = Gv.q + c  (warp per row) --------------------
__global__ void growdot_kernel(const float* __restrict__ seq) {
    int r = blockIdx.x * 8 + (threadIdx.x >> 5);
    int lane = threadIdx.x & 31;
    int which = blockIdx.y;
    const int* gidx = which ? g_vidx : g_kidx;
    const float* vec = which ? g_q : g_p;
    const float* row = seq + ((long long)(r >> 7) * SS + gidx[r]) * HH;
    float s = 0.f;
    #pragma unroll 4
    for (int cdx = lane; cdx < HH; cdx += 32) s = fmaf(row[cdx], vec[cdx], s);
    #pragma unroll
    for (int o = 16; o; o >>= 1) s += __shfl_xor_sync(0xffffffffu, s, o);
    if (lane == 0) {
        if (which) g_rowv[r] = s + g_c[0];
        else       g_rowk[r] = s;
    }
}

// ----- biaffine: biaf4[s][b,i,j] = u[b,i,ks] . Gv_seq[b,j,ks] (4 splits) ---
__global__ __launch_bounds__(512)
void biaf_splitk(const float* __restrict__ seq) {
    __shared__ __align__(16) float As[2][TK][132];
    __shared__ __align__(16) float Bs[2][TK][132];
    __shared__ long long vrowbase[128];
    const int nslabs = 12;
    int b = blockIdx.y;
    int split = blockIdx.x;
    int kbase = split * nslabs * TK;
    int tid = threadIdx.x;
    int tx = tid & 15, ty = tid >> 4;

    const float* A = g_u + (long long)b * MC * HH;

    if (tid < 128)
        vrowbase[tid] = ((long long)b * SS + g_vidx[b * MC + tid]) * HH;
    __syncthreads();

    int ar = tid >> 2, ak = (tid & 3) * 4;
    long long vb = vrowbase[ar];

    float4 av, bv4;
#define LOAD(K0) do { \
        av  = *(const float4*)(A + (long long)ar * HH + (K0) + ak); \
        bv4 = *(const float4*)(seq + vb + (K0) + ak); \
    } while (0)
#define STORE(BUF) do { \
        As[BUF][ak+0][ar] = av.x; As[BUF][ak+1][ar] = av.y; \
        As[BUF][ak+2][ar] = av.z; As[BUF][ak+3][ar] = av.w; \
        Bs[BUF][ak+0][ar] = bv4.x; Bs[BUF][ak+1][ar] = bv4.y; \
        Bs[BUF][ak+2][ar] = bv4.z; Bs[BUF][ak+3][ar] = bv4.w; \
    } while (0)

    float acc[4][8];
    #pragma unroll
    for (int i = 0; i < 4; i++)
        #pragma unroll
        for (int j = 0; j < 8; j++) acc[i][j] = 0.f;

    LOAD(kbase); STORE(0); __syncthreads();
    for (int kt = 0; kt < nslabs; kt++) {
        int cur = kt & 1;
        if (kt + 1 < nslabs) LOAD(kbase + (kt + 1) * TK);
        #pragma unroll
        for (int kk = 0; kk < TK; kk++) {
            float a[4], bb[8];
            *(float4*)a        = *(const float4*)&As[cur][kk][ty * 4];
            *(float4*)bb       = *(const float4*)&Bs[cur][kk][tx * 8];
            *(float4*)(bb + 4) = *(const float4*)&Bs[cur][kk][tx * 8 + 4];
            #pragma unroll
            for (int i = 0; i < 4; i++)
                #pragma unroll
                for (int j = 0; j < 8; j++)
                    acc[i][j] = fmaf(a[i], bb[j], acc[i][j]);
        }
        if (kt + 1 < nslabs) { STORE(cur ^ 1); __syncthreads(); }
    }

    float* dst = g_biaf4[split] + (long long)b * (MC * MC);
    #pragma unroll
    for (int i = 0; i < 4; i++) {
        int r = ty * 4 + i;
        *(float4*)&dst[r * MC + tx * 8]     = *(float4*)&acc[i][0];
        *(float4*)&dst[r * MC + tx * 8 + 4] = *(float4*)&acc[i][4];
    }
#undef LOAD
#undef STORE
}

// ---------------- spatial features + folded MLP + final scores ------------
__global__ __launch_bounds__(128)
void pair_kernel(float* __restrict__ out,
                 const float* __restrict__ Ws1, const float* __restrict__ bs1,
                 const float* __restrict__ Wf1,
                 const float* __restrict__ Wf2, const float* __restrict__ bf2,
                 const float* __restrict__ bbilp) {
    __shared__ float sW1[8 * 64], sb1[64];
    __shared__ float sW2f[64 * 16], sb2f[16];
    __shared__ float sF0[16], sF2[16];
    __shared__ float sbf2, sbil, srowk;
    __shared__ float kb[4];

    int i = blockIdx.x;
    int b = blockIdx.y;
    int j = threadIdx.x;

    for (int t = j; t < 512;  t += 128) sW1[t] = Ws1[t];
    for (int t = j; t < 1024; t += 128) sW2f[t] = g_W2f[t];
    if (j < 64) sb1[j] = bs1[j];
    if (j < 16) { sb2f[j] = g_b2f[j]; sF0[j] = Wf1[j]; sF2[j] = Wf2[j]; }
    if (j == 0) { sbf2 = bf2[0]; sbil = bbilp[0]; srowk = g_rowk[b * MC + i]; }
    if (j < 4)  kb[j] = g_kbox[(b * MC + i) * 4 + j];
    __syncthreads();

    float vx1 = g_vbox[(b * MC + j) * 4 + 0];
    float vy1 = g_vbox[(b * MC + j) * 4 + 1];
    float vx2 = g_vbox[(b * MC + j) * 4 + 2];
    float vy2 = g_vbox[(b * MC + j) * 4 + 3];
    float kx1 = kb[0], ky1 = kb[1], kx2 = kb[2], ky2 = kb[3];

    float kcx = (kx1 + kx2) * 0.5f, kcy = (ky1 + ky2) * 0.5f;
    float vcx = (vx1 + vx2) * 0.5f, vcy = (vy1 + vy2) * 0.5f;
    float dx = vcx - kcx, dy = vcy - kcy;
    float dist  = sqrtf(dx * dx + dy * dy + EPSF);
    float angle = atan2f(dy, dx);
    float kh = ky2 - ky1, kw = kx2 - kx1;
    float vh = vy2 - vy1, vw = vx2 - vx1;
    float h_ov = fmaxf(fminf(ky2, vy2) - fmaxf(ky1, vy1), 0.0f);
    float h_align = h_ov / (fminf(kh, vh) + EPSF);
    float v_ov = fmaxf(fminf(kx2, vx2) - fmaxf(kx1, vx1), 0.0f);
    float v_align = v_ov / (fminf(kw, vw) + EPSF);
    float area_ratio   = (vh * vw) / (kh * kw + EPSF);
    float aspect_ratio = (vw / (vh + EPSF)) / (kw / (kh + EPSF));

    float sf[8] = { dx, dy, dist, angle, h_align, v_align, area_ratio, aspect_ratio };

    long long bidx = (long long)b * (MC * MC) + i * MC + j;
    float biafv = g_biaf4[0][bidx] + g_biaf4[1][bidx]
                + g_biaf4[2][bidx] + g_biaf4[3][bidx]
                + srowk + g_rowv[b * MC + j] + sbil;

    float f1[16];
    #pragma unroll
    for (int t = 0; t < 16; t++) f1[t] = fmaf(biafv, sF0[t], sb2f[t]);

    for (int u = 0; u < 64; u++) {
        float h = sb1[u];
        #pragma unroll
        for (int f = 0; f < 8; f++) h = fmaf(sf[f], sW1[f * 64 + u], h);
        h = fmaxf(h, 0.0f);
        #pragma unroll
        for (int t = 0; t < 16; t++) f1[t] = fmaf(h, sW2f[u * 16 + t], f1[t]);
    }

    float score = sbf2;
    #pragma unroll
    for (int t = 0; t < 16; t++) score = fmaf(fmaxf(f1[t], 0.0f), sF2[t], score);

    out[bidx] = score;
}

// ---------------- launch ----------------
extern "C" void kernel_launch(void* const* d_in, const int* in_sizes, int n_in,
                              void* d_out, int out_size) {
    (void)in_sizes; (void)n_in; (void)out_size;
    const float* seq    = (const float*)d_in[0];
    const float* logits = (const float*)d_in[1];
    const float* bboxes = (const float*)d_in[2];
    const int*   mask   = (const int*)  d_in[3];
    const float* Wk  = (const float*)d_in[4];
    const float* bk  = (const float*)d_in[5];
    const float* Wv  = (const float*)d_in[6];
    const float* bv  = (const float*)d_in[7];
    const float* Wbil= (const float*)d_in[8];
    const float* bbil= (const float*)d_in[9];
    const float* Ws1 = (const float*)d_in[10];
    const float* bs1 = (const float*)d_in[11];
    const float* Ws2 = (const float*)d_in[12];
    const float* bs2 = (const float*)d_in[13];
    const float* Wf1 = (const float*)d_in[14];
    const float* bf1 = (const float*)d_in[15];
    const float* Wf2 = (const float*)d_in[16];
    const float* bf2 = (const float*)d_in[17];
    float* out = (float*)d_out;

    float *pWc2, *pM;
    cudaGetSymbolAddress((void**)&pWc2, g_Wc2);
    cudaGetSymbolAddress((void**)&pM,   g_M);

    cudaMemsetAsync(pWc2, 0, (size_t)HH * HH * sizeof(float));
    cudaMemsetAsync(pM,   0, (size_t)HH * HH * sizeof(float));

    topk_kernel<<<dim3(BB, 2), 512>>>(logits, mask, bboxes, out);
    setupA<<<99, 256>>>(bk, Wbil, bv);
    setupB<<<193, 256>>>(Wv, Wk, bv, Ws2, bs2, Wf1, bf1);

    // Wc2 = Wbil @ Wv^T  (split-K x4, 144 blocks, 512 threads)
    nt_atomic<<<dim3(HH / 128, HH / 128, 4), 512>>>(Wbil, Wv, pWc2);
    // M = Wk @ Wc2
    nn_atomic<<<dim3(HH / 128, HH / 128, 4), 512>>>(Wk, pWc2, pM);

    // u = Gk(seq) @ M   (full K, 192 blocks)
    u_gemm<<<dim3(HH / 128, (BB * MC) / 128), 256>>>(seq, pM);

    // rowk = Gk.p ; rowv = Gv.q + c
    growdot_kernel<<<dim3((BB * MC) / 8, 2), 256>>>(seq);

    // biaffine term1: 4 split buffers
    biaf_splitk<<<dim3(4, BB), 512>>>(seq);

    pair_kernel<<<dim3(MC, BB), 128>>>(out, Ws1, bs1, Wf1, Wf2, bf2, bbil);
}